// round 10
// baseline (speedup 1.0000x reference)
#include <cuda_runtime.h>
#include <cuda_fp16.h>
#include <cstdint>
#include <cstddef>

// ---------------------------------------------------------------------------
// GCN_27874337751415 round 10: chunked agg->gemm pipelining across streams
// (row-block-aligned dependency), separate H2 buffer to break WAR hazard.
// ---------------------------------------------------------------------------

#define MAXN 50176
#define MAXE 800000
#define NCHUNK 4

__device__ int   g_deg[MAXN];
__device__ int   g_off[MAXN + 1];
__device__ int   g_cur[MAXN];
__device__ int   g_flag[64];
__device__ int2  g_sw[MAXE];                                // {src, f32 wt bits}
__device__ __align__(16) __half g_H[(size_t)MAXN * 256];   // gemm1/3 out
__device__ __align__(16) __half g_H2[(size_t)MAXN * 128];  // gemm2 out
__device__ __align__(16) float  g_A[(size_t)MAXN * 64];    // layer-3 agg out
__device__ __align__(16) __half g_X[(size_t)MAXN * 256];   // agg out = GEMM A
__device__ __align__(16) __half g_B1[512 * 256];
__device__ __align__(16) __half g_B2[256 * 128];
__device__ __align__(16) __half g_B3[128 * 64];
__device__ int   g_ei64;
__device__ int   g_b64;

// ---------------------------------------------------------------------------
// helpers
// ---------------------------------------------------------------------------
__device__ __forceinline__ uint32_t smem_u32(const void* p) {
    uint32_t a;
    asm("{ .reg .u64 t; cvta.to.shared.u64 t, %1; cvt.u32.u64 %0, t; }"
        : "=r"(a) : "l"(p));
    return a;
}
__device__ __forceinline__ void cpa16(uint32_t s, const void* g) {
    asm volatile("cp.async.cg.shared.global [%0], [%1], 16;" :: "r"(s), "l"(g));
}
#define LDM4(r, addr)                                                         \
    asm volatile("ldmatrix.sync.aligned.m8n8.x4.shared.b16 {%0,%1,%2,%3}, [%4];" \
                 : "=r"((r)[0]), "=r"((r)[1]), "=r"((r)[2]), "=r"((r)[3])     \
                 : "r"(addr))
#define MMAF16(c, a, b)                                                       \
    asm volatile("mma.sync.aligned.m16n8k16.row.col.f32.f16.f16.f32 "         \
                 "{%0,%1,%2,%3},{%4,%5,%6,%7},{%8,%9},{%0,%1,%2,%3};"         \
                 : "+f"((c)[0]), "+f"((c)[1]), "+f"((c)[2]), "+f"((c)[3])     \
                 : "r"((a)[0]), "r"((a)[1]), "r"((a)[2]), "r"((a)[3]),        \
                   "r"((b)[0]), "r"((b)[1]))

// 64-byte rows, 16B chunks, chunk ^= (row>>1)&3 -> ldmatrix conflict-free
__device__ __forceinline__ uint32_t tile_off(int row, int chunk) {
    return (uint32_t)(row * 64 + ((chunk ^ ((row >> 1) & 3)) * 16));
}

// ---------------------------------------------------------------------------
// dtype detection + zeroing of g_deg / g_flag (block 0 detects, all zero)
// ---------------------------------------------------------------------------
__global__ void k_detect(const unsigned* __restrict__ ei,
                         const unsigned* __restrict__ bat, int E, int N) {
    int gid = blockIdx.x * blockDim.x + threadIdx.x;
    for (int i = gid; i < MAXN; i += gridDim.x * blockDim.x) g_deg[i] = 0;
    if (gid < 64) g_flag[gid] = 0;
    if (blockIdx.x == 0) {
        __shared__ int s_ei, s_b;
        if (threadIdx.x == 0) { s_ei = 0; s_b = 0; }
        __syncthreads();
        int ne = (E < 1024) ? E : 1024;
        for (int i = threadIdx.x; i < ne; i += blockDim.x)
            if (ei[2 * i + 1]) atomicOr(&s_ei, 1);
        int base = N / 2 - 256; if (base < 0) base = 0;
        int nb2 = (N / 2 > 256) ? 256 : N / 2;
        for (int j = threadIdx.x; j < nb2; j += blockDim.x)
            if (bat[2 * (base + j) + 1]) atomicOr(&s_b, 1);
        __syncthreads();
        if (threadIdx.x == 0) { g_ei64 = s_ei ? 0 : 1; g_b64 = s_b ? 0 : 1; }
    }
}

__device__ __forceinline__ int load_idx(const void* p, int i, int is64) {
    return is64 ? (int)((const long long*)p)[i] : ((const int*)p)[i];
}

// ---------------------------------------------------------------------------
// CSR-by-dst preprocessing
// ---------------------------------------------------------------------------
__global__ void k_hist(const void* __restrict__ ei, int E) {
    int e = blockIdx.x * blockDim.x + threadIdx.x;
    if (e >= E) return;
    atomicAdd(&g_deg[load_idx(ei, E + e, g_ei64)], 1);
}

// Single-pass exclusive scan, warp-parallel decoupled lookback.
__global__ void k_scan1(const int* __restrict__ in, int* __restrict__ off,
                        int* __restrict__ cur, int n, int E) {
    __shared__ int s[1024];
    __shared__ int s_pfx;
    int bid = blockIdx.x;
    int gid = bid * 1024 + threadIdx.x;
    int v = (gid < n) ? in[gid] : 0;
    s[threadIdx.x] = v;
    __syncthreads();
    #pragma unroll
    for (int d = 1; d < 1024; d <<= 1) {
        int t = (threadIdx.x >= d) ? s[threadIdx.x - d] : 0;
        __syncthreads();
        s[threadIdx.x] += t;
        __syncthreads();
    }
    if (threadIdx.x < 32) {
        if (threadIdx.x == 0)
            atomicExch(&g_flag[bid], s[1023] + 1);
        int pfx = 0;
        for (int i = threadIdx.x; i < bid; i += 32) {
            int f;
            while ((f = atomicAdd(&g_flag[i], 0)) == 0) {}
            pfx += f - 1;
        }
        #pragma unroll
        for (int o = 16; o > 0; o >>= 1)
            pfx += __shfl_down_sync(0xFFFFFFFFu, pfx, o);
        if (threadIdx.x == 0) s_pfx = pfx;
    }
    __syncthreads();
    if (gid < n) {
        int o = s_pfx + s[threadIdx.x] - v;
        off[gid] = o;
        cur[gid] = o;
    }
    if (bid == (int)gridDim.x - 1 && threadIdx.x == 1023) off[n] = E;
}

__global__ void k_scatter(const void* __restrict__ ei, int E) {
    int e = blockIdx.x * blockDim.x + threadIdx.x;
    if (e >= E) return;
    int is64 = g_ei64;
    int s = load_idx(ei, e, is64);
    int d = load_idx(ei, E + e, is64);
    int p = atomicAdd(&g_cur[d], 1);
    float w = rsqrtf((float)(g_deg[s] + 1));
    g_sw[p] = make_int2(s, __float_as_int(w));
}

// All three weights, transposed to [N x K] fp16, in one launch.
__global__ void k_cvtW(const float* __restrict__ W1, const float* __restrict__ W2,
                       const float* __restrict__ W3) {
    int t = blockIdx.x * blockDim.x + threadIdx.x;
    if (t < 131072) {
        int n = t >> 9, k = t & 511;
        g_B1[t] = __float2half_rn(W1[(size_t)k * 256 + n]);
    } else if (t < 131072 + 32768) {
        int u = t - 131072;
        int n = u >> 8, k = u & 255;
        g_B2[u] = __float2half_rn(W2[(size_t)k * 128 + n]);
    } else if (t < 131072 + 32768 + 8192) {
        int u = t - 163840;
        int n = u >> 7, k = u & 127;
        g_B3[u] = __float2half_rn(W3[(size_t)k * 64 + n]);
    }
}

// ---------------------------------------------------------------------------
// HMMA GEMM: C[M,N] = A[M,K] @ B[N,K]^T, fp32 accum, fp16 out.
// m_off: tile offset for chunked launches. Grid (n-tiles, m-tiles-in-chunk).
// ---------------------------------------------------------------------------
template<int BN, bool CVT>
__global__ void __launch_bounds__(256, 1) k_gemm_mma(
    const void* __restrict__ Av, const __half* __restrict__ B,
    __half* __restrict__ C, int M, int N, int K, int m_off)
{
    constexpr int SS = 8192 + BN * 64;
    constexpr int NT = BN / 16;
    constexpr int WN = BN / 2;
    extern __shared__ char smem[];
    uint32_t sb = smem_u32(smem);
    int tid = threadIdx.x, lane = tid & 31, wid = tid >> 5;
    int bm = (m_off + blockIdx.y) * 128, bn = blockIdx.x * BN;
    int warp_m = wid & 3, warp_n = wid >> 2;
    const __half* A = (const __half*)Av;
    const float* Af = (const float*)Av;

    float acc[2][NT][4] = {};
    const int KC = K >> 5;
    float4 a4[4];

    auto ldgA = [&](int it) {
        int k0 = it << 5;
        #pragma unroll
        for (int u = 0; u < 4; u++) {
            int c = u * 256 + tid;
            int row = c >> 3, ch8 = c & 7;
            int grow = bm + row;
            if (grow < M)
                a4[u] = *(const float4*)(Af + (size_t)grow * K + k0 + ch8 * 4);
            else
                a4[u] = make_float4(0.f, 0.f, 0.f, 0.f);
        }
    };
    auto stsA = [&](int s) {
        uint32_t base = sb + s * SS;
        #pragma unroll
        for (int u = 0; u < 4; u++) {
            int c = u * 256 + tid;
            int row = c >> 3, ch8 = c & 7;
            uint32_t off = tile_off(row, ch8 >> 1) + (ch8 & 1) * 8;
            __half2 h0 = __floats2half2_rn(a4[u].x, a4[u].y);
            __half2 h1 = __floats2half2_rn(a4[u].z, a4[u].w);
            asm volatile("st.shared.v2.b32 [%0], {%1,%2};"
                         :: "r"(base + off), "r"(*(uint32_t*)&h0), "r"(*(uint32_t*)&h1));
        }
    };
    auto ldA_async = [&](int it, int s) {
        int k0 = it << 5;
        uint32_t base = sb + s * SS;
        #pragma unroll
        for (int u = 0; u < 2; u++) {
            int c = tid * 2 + u;
            int row = c >> 2, ch = c & 3;
            cpa16(base + tile_off(row, ch), A + (size_t)(bm + row) * K + k0 + ch * 8);
        }
    };
    auto ldB = [&](int it, int s) {
        int k0 = it << 5;
        uint32_t base = sb + s * SS;
        #pragma unroll
        for (int u = 0; u < BN / 64; u++) {
            int c = tid + u * 256;
            int row = c >> 2, ch = c & 3;
            cpa16(base + 8192 + tile_off(row, ch), B + (size_t)(bn + row) * K + k0 + ch * 8);
        }
    };

    if constexpr (CVT) {
        ldgA(0);
        ldB(0, 0);
        asm volatile("cp.async.commit_group;");
        stsA(0);
    } else {
        ldA_async(0, 0);
        ldB(0, 0);
        asm volatile("cp.async.commit_group;");
    }

    int a_row = warp_m * 32 + (lane & 15);
    int a_chi = lane >> 4;
    int blk = lane >> 3;
    int b_rl = ((blk >> 1) * 8) + (lane & 7);
    int b_chi = blk & 1;

    for (int it = 0; it < KC; it++) {
        int s = it & 1;
        if (it + 1 < KC) {
            if constexpr (CVT) {
                ldgA(it + 1);
                ldB(it + 1, s ^ 1);
            } else {
                ldA_async(it + 1, s ^ 1);
                ldB(it + 1, s ^ 1);
            }
            asm volatile("cp.async.commit_group;");
            asm volatile("cp.async.wait_group 1;");
        } else {
            asm volatile("cp.async.wait_group 0;");
        }
        __syncthreads();
        uint32_t base = sb + s * SS;
        #pragma unroll
        for (int kk = 0; kk < 2; kk++) {
            uint32_t af[2][4];
            int ach = kk * 2 + a_chi;
            #pragma unroll
            for (int mt = 0; mt < 2; mt++) {
                uint32_t off = tile_off(a_row + mt * 16, ach);
                LDM4(af[mt], base + off);
            }
            #pragma unroll
            for (int h = 0; h < NT / 4; h++) {
                uint32_t bf[4][2];
                #pragma unroll
                for (int nt2 = 0; nt2 < 2; nt2++) {
                    uint32_t r4[4];
                    int brow = warp_n * WN + h * 32 + nt2 * 16 + b_rl;
                    uint32_t off = tile_off(brow, kk * 2 + b_chi);
                    LDM4(r4, base + 8192 + off);
                    bf[nt2 * 2][0] = r4[0]; bf[nt2 * 2][1] = r4[1];
                    bf[nt2 * 2 + 1][0] = r4[2]; bf[nt2 * 2 + 1][1] = r4[3];
                }
                #pragma unroll
                for (int mt = 0; mt < 2; mt++)
                    #pragma unroll
                    for (int j = 0; j < 4; j++)
                        MMAF16(acc[mt][h * 4 + j], af[mt], bf[j]);
            }
        }
        __syncthreads();
        if constexpr (CVT) {
            if (it + 1 < KC) stsA(s ^ 1);
        }
    }

    #pragma unroll
    for (int mt = 0; mt < 2; mt++)
        #pragma unroll
        for (int nt = 0; nt < NT; nt++) {
            int row0 = bm + warp_m * 32 + mt * 16 + (lane >> 2);
            int col = bn + warp_n * WN + nt * 8 + (lane & 3) * 2;
            if (row0 < M)
                *(__half2*)(C + (size_t)row0 * N + col) =
                    __floats2half2_rn(acc[mt][nt][0], acc[mt][nt][1]);
            if (row0 + 8 < M)
                *(__half2*)(C + (size_t)(row0 + 8) * N + col) =
                    __floats2half2_rn(acc[mt][nt][2], acc[mt][nt][3]);
        }
}

// ---------------------------------------------------------------------------
// Aggregation over fp16 H: Out[v] = dinv[v]*(dinv[v]*H[v] + sum wt*H[src]) + b
// vbase: row offset for chunked launches.
// ---------------------------------------------------------------------------
__global__ void k_agg(const __half* __restrict__ Hin, float* __restrict__ OutF,
                      __half* __restrict__ OutH,
                      const float* __restrict__ bias, int N, int Mpad, int relu,
                      int vbase) {
    int v = vbase + blockIdx.x * blockDim.y + threadIdx.y;
    if (v >= Mpad) return;
    int F8 = blockDim.x;
    int x = threadIdx.x;
    int F = F8 * 8;
    if (v >= N) {
        if (OutH)
            ((uint4*)(OutH + (size_t)v * F))[x] = make_uint4(0, 0, 0, 0);
        return;
    }
    const uint4* H4 = (const uint4*)Hin;
    float dv = rsqrtf((float)(g_deg[v] + 1));
    float acc[8];
    {
        uint4 hv = H4[(size_t)v * F8 + x];
        const __half2* p = (const __half2*)&hv;
        #pragma unroll
        for (int q = 0; q < 4; q++) {
            float2 f = __half22float2(p[q]);
            acc[q * 2] = dv * f.x;
            acc[q * 2 + 1] = dv * f.y;
        }
    }
    int e = g_off[v], end = g_off[v + 1];
    for (; e + 7 < end; e += 8) {
        int2 sw[8]; uint4 hv[8];
        #pragma unroll
        for (int j = 0; j < 8; j++)
            sw[j] = __ldg(&g_sw[e + j]);
        #pragma unroll
        for (int j = 0; j < 8; j++)
            hv[j] = H4[(size_t)sw[j].x * F8 + x];
        #pragma unroll
        for (int j = 0; j < 8; j++) {
            float w = __int_as_float(sw[j].y);
            const __half2* p = (const __half2*)&hv[j];
            #pragma unroll
            for (int q = 0; q < 4; q++) {
                float2 f = __half22float2(p[q]);
                acc[q * 2]     += w * f.x;
                acc[q * 2 + 1] += w * f.y;
            }
        }
    }
    for (; e + 3 < end; e += 4) {
        int2 sw[4]; uint4 hv[4];
        #pragma unroll
        for (int j = 0; j < 4; j++)
            sw[j] = __ldg(&g_sw[e + j]);
        #pragma unroll
        for (int j = 0; j < 4; j++)
            hv[j] = H4[(size_t)sw[j].x * F8 + x];
        #pragma unroll
        for (int j = 0; j < 4; j++) {
            float w = __int_as_float(sw[j].y);
            const __half2* p = (const __half2*)&hv[j];
            #pragma unroll
            for (int q = 0; q < 4; q++) {
                float2 f = __half22float2(p[q]);
                acc[q * 2]     += w * f.x;
                acc[q * 2 + 1] += w * f.y;
            }
        }
    }
    for (; e < end; e++) {
        int2 sw = __ldg(&g_sw[e]);
        float w = __int_as_float(sw.y);
        uint4 h0 = H4[(size_t)sw.x * F8 + x];
        const __half2* p0 = (const __half2*)&h0;
        #pragma unroll
        for (int q = 0; q < 4; q++) {
            float2 f0 = __half22float2(p0[q]);
            acc[q * 2]     += w * f0.x;
            acc[q * 2 + 1] += w * f0.y;
        }
    }
    float o[8];
    {
        float4 b0 = ((const float4*)bias)[x * 2];
        float4 b1 = ((const float4*)bias)[x * 2 + 1];
        o[0] = dv * acc[0] + b0.x; o[1] = dv * acc[1] + b0.y;
        o[2] = dv * acc[2] + b0.z; o[3] = dv * acc[3] + b0.w;
        o[4] = dv * acc[4] + b1.x; o[5] = dv * acc[5] + b1.y;
        o[6] = dv * acc[6] + b1.z; o[7] = dv * acc[7] + b1.w;
    }
    if (relu) {
        #pragma unroll
        for (int q = 0; q < 8; q++) o[q] = fmaxf(o[q], 0.f);
    }
    if (OutF) {
        float4* d = (float4*)(OutF + (size_t)v * F + x * 8);
        d[0] = make_float4(o[0], o[1], o[2], o[3]);
        d[1] = make_float4(o[4], o[5], o[6], o[7]);
    }
    if (OutH) {
        __half2 hh[4];
        #pragma unroll
        for (int q = 0; q < 4; q++)
            hh[q] = __floats2half2_rn(o[q * 2], o[q * 2 + 1]);
        ((uint4*)(OutH + (size_t)v * F))[x] = *(uint4*)hh;
    }
}

// ---------------------------------------------------------------------------
// Fused mean-pool + head: one block per graph (batch sorted).
// ---------------------------------------------------------------------------
__global__ void k_poolfinal(const float* __restrict__ Afin,
                            const void* __restrict__ bat,
                            const float* __restrict__ Wl,
                            const float* __restrict__ bl,
                            float* __restrict__ out, int N) {
    int g = blockIdx.x;
    int t = threadIdx.x;
    int is64 = g_b64;
    int lo = 0, hi = N;
    while (lo < hi) { int m = (lo + hi) >> 1; if (load_idx(bat, m, is64) < g) lo = m + 1; else hi = m; }
    int lo2 = lo, hi2 = N;
    while (lo2 < hi2) { int m = (lo2 + hi2) >> 1; if (load_idx(bat, m, is64) < g + 1) lo2 = m + 1; else hi2 = m; }
    int f = t & 63, seg = t >> 6;
    float acc = 0.f;
    for (int v = lo + seg; v < lo2; v += 4)
        acc += Afin[(size_t)v * 64 + f];
    __shared__ float sm[256];
    __shared__ float pooled[64];
    sm[t] = acc;
    __syncthreads();
    if (t < 64)
        pooled[t] = sm[t] + sm[t + 64] + sm[t + 128] + sm[t + 192];
    __syncthreads();
    if (t < 2) {
        float cnt = fmaxf((float)(lo2 - lo), 1.0f);
        float s = 0.f;
        #pragma unroll
        for (int ff = 0; ff < 64; ff++) s += pooled[ff] * Wl[ff * 2 + t];
        out[g * 2 + t] = s / cnt + bl[t];
    }
}

// ---------------------------------------------------------------------------
// Orchestration
// ---------------------------------------------------------------------------
extern "C" void kernel_launch(void* const* d_in, const int* in_sizes, int n_in,
                              void* d_out, int out_size) {
    const float* x   = (const float*)d_in[0];
    const void*  ei  = d_in[1];
    const void*  bat = d_in[2];
    const float* W1 = (const float*)d_in[3];
    const float* b1 = (const float*)d_in[4];
    const float* W2 = (const float*)d_in[5];
    const float* b2 = (const float*)d_in[6];
    const float* W3 = (const float*)d_in[7];
    const float* b3 = (const float*)d_in[8];
    const float* Wl = (const float*)d_in[9];
    const float* bl = (const float*)d_in[10];
    float* out = (float*)d_out;

    int N = in_sizes[0] / 512;
    int E = in_sizes[1] / 2;
    int G = out_size / 2;
    int mt = (N + 127) / 128;
    int Mpad = mt * 128;

    static int inited = 0;
    static cudaStream_t s2, s3;
    static cudaEvent_t ev1, ev_w, ev_csr, ev_g2, ev_g3;
    static cudaEvent_t ev_c1[NCHUNK], ev_c2[NCHUNK];
    if (!inited) {
        cudaFuncSetAttribute((const void*)k_gemm_mma<128, true>,
                             cudaFuncAttributeMaxDynamicSharedMemorySize, 32768);
        cudaFuncSetAttribute((const void*)k_gemm_mma<128, false>,
                             cudaFuncAttributeMaxDynamicSharedMemorySize, 32768);
        cudaFuncSetAttribute((const void*)k_gemm_mma<64, false>,
                             cudaFuncAttributeMaxDynamicSharedMemorySize, 24576);
        cudaStreamCreateWithFlags(&s2, cudaStreamNonBlocking);
        cudaStreamCreateWithFlags(&s3, cudaStreamNonBlocking);
        cudaEventCreateWithFlags(&ev1, cudaEventDisableTiming);
        cudaEventCreateWithFlags(&ev_w, cudaEventDisableTiming);
        cudaEventCreateWithFlags(&ev_csr, cudaEventDisableTiming);
        cudaEventCreateWithFlags(&ev_g2, cudaEventDisableTiming);
        cudaEventCreateWithFlags(&ev_g3, cudaEventDisableTiming);
        for (int c = 0; c < NCHUNK; c++) {
            cudaEventCreateWithFlags(&ev_c1[c], cudaEventDisableTiming);
            cudaEventCreateWithFlags(&ev_c2[c], cudaEventDisableTiming);
        }
        inited = 1;
    }

    void *p_deg, *p_off, *p_cur, *p_H, *p_H2, *p_A, *p_X, *p_B1, *p_B2, *p_B3;
    cudaGetSymbolAddress(&p_deg, g_deg);
    cudaGetSymbolAddress(&p_off, g_off);
    cudaGetSymbolAddress(&p_cur, g_cur);
    cudaGetSymbolAddress(&p_H, g_H);
    cudaGetSymbolAddress(&p_H2, g_H2);
    cudaGetSymbolAddress(&p_A, g_A);
    cudaGetSymbolAddress(&p_X, g_X);
    cudaGetSymbolAddress(&p_B1, g_B1);
    cudaGetSymbolAddress(&p_B2, g_B2);
    cudaGetSymbolAddress(&p_B3, g_B3);

    // ---- fork -----------------------------------------------------------
    cudaEventRecord(ev1, 0);
    cudaStreamWaitEvent(s2, ev1, 0);
    cudaStreamWaitEvent(s3, ev1, 0);
    // s3: weight convert only (gates gemm1)
    k_cvtW<<<(172032 + 255) / 256, 256, 0, s3>>>(W1, W2, W3);
    cudaEventRecord(ev_w, s3);
    // s2: CSR build (gates agg1)
    k_detect<<<64, 256, 0, s2>>>((const unsigned*)ei, (const unsigned*)bat, E, N);
    k_hist<<<(E + 255) / 256, 256, 0, s2>>>(ei, E);
    int nb = (N + 1023) / 1024;
    k_scan1<<<nb, 1024, 0, s2>>>((const int*)p_deg, (int*)p_off, (int*)p_cur, N, E);
    k_scatter<<<(E + 255) / 256, 256, 0, s2>>>(ei, E);
    cudaEventRecord(ev_csr, s2);

    // ---- layer-1 GEMM with fused fp32->fp16 conversion ------------------
    cudaStreamWaitEvent(0, ev_w, 0);
    k_gemm_mma<128, true><<<dim3(2, mt), 256, 32768>>>(
        x, (const __half*)p_B1, (__half*)p_H, N, 256, 512, 0);

    // ---- join + pipelined agg1 -> gemm2 ---------------------------------
    cudaStreamWaitEvent(0, ev_csr, 0);
    int CT = (mt + NCHUNK - 1) / NCHUNK;   // tiles per chunk
    for (int c = 0; c < NCHUNK; c++) {
        int t0 = c * CT;
        int t1 = (t0 + CT < mt) ? t0 + CT : mt;
        if (t0 >= t1) break;
        int r0 = t0 * 128, rows = (t1 - t0) * 128;
        k_agg<<<rows / 8, dim3(32, 8)>>>((const __half*)p_H, nullptr,
                                         (__half*)p_X, b1, N, Mpad, 1, r0);
        cudaEventRecord(ev_c1[c], 0);
        cudaStreamWaitEvent(s3, ev_c1[c], 0);
        k_gemm_mma<128, false><<<dim3(1, t1 - t0), 256, 32768, s3>>>(
            p_X, (const __half*)p_B2, (__half*)p_H2, N, 128, 256, t0);
    }
    cudaEventRecord(ev_g2, s3);
    cudaStreamWaitEvent(0, ev_g2, 0);

    // ---- pipelined agg2 -> gemm3 ----------------------------------------
    for (int c = 0; c < NCHUNK; c++) {
        int t0 = c * CT;
        int t1 = (t0 + CT < mt) ? t0 + CT : mt;
        if (t0 >= t1) break;
        int r0 = t0 * 128, rows = (t1 - t0) * 128;
        k_agg<<<rows / 16, dim3(16, 16)>>>((const __half*)p_H2, nullptr,
                                           (__half*)p_X, b2, N, Mpad, 1, r0);
        cudaEventRecord(ev_c2[c], 0);
        cudaStreamWaitEvent(s3, ev_c2[c], 0);
        k_gemm_mma<64, false><<<dim3(1, t1 - t0), 256, 24576, s3>>>(
            p_X, (const __half*)p_B3, (__half*)p_H, N, 64, 128, t0);
    }
    cudaEventRecord(ev_g3, s3);
    cudaStreamWaitEvent(0, ev_g3, 0);

    // ---- layer-3 aggregation + fused pool/head --------------------------
    {
        int gb = (N + 31) / 32;
        k_agg<<<gb, dim3(8, 32)>>>((const __half*)p_H, (float*)p_A,
                                   nullptr, b3, N, N, 0, 0);
    }
    k_poolfinal<<<G, 256>>>((const float*)p_A, bat, Wl, bl, out, N);
}

// round 11
// speedup vs baseline: 1.1208x; 1.1208x over previous
#include <cuda_runtime.h>
#include <cuda_fp16.h>
#include <cstdint>
#include <cstddef>

// ---------------------------------------------------------------------------
// GCN_27874337751415 round 11: revert R10 chunk-pipelining (cross-stream
// edges cost ~3us each in this harness). R9 schedule + cvtW moved onto
// stream 0 (drops 2 cross-stream edges), warp-shuffle scan, 2-edge/thread
// hist+scatter.
// ---------------------------------------------------------------------------

#define MAXN 50176
#define MAXE 800000

__device__ int   g_deg[MAXN];
__device__ int   g_off[MAXN + 1];
__device__ int   g_cur[MAXN];
__device__ int   g_flag[64];
__device__ int2  g_sw[MAXE];                                // {src, f32 wt bits}
__device__ __align__(16) __half g_H[(size_t)MAXN * 256];   // GEMM out, fp16
__device__ __align__(16) float  g_A[(size_t)MAXN * 64];    // layer-3 agg out
__device__ __align__(16) __half g_X[(size_t)MAXN * 256];   // agg out = GEMM A
__device__ __align__(16) __half g_B1[512 * 256];
__device__ __align__(16) __half g_B2[256 * 128];
__device__ __align__(16) __half g_B3[128 * 64];
__device__ int   g_ei64;
__device__ int   g_b64;

// ---------------------------------------------------------------------------
// helpers
// ---------------------------------------------------------------------------
__device__ __forceinline__ uint32_t smem_u32(const void* p) {
    uint32_t a;
    asm("{ .reg .u64 t; cvta.to.shared.u64 t, %1; cvt.u32.u64 %0, t; }"
        : "=r"(a) : "l"(p));
    return a;
}
__device__ __forceinline__ void cpa16(uint32_t s, const void* g) {
    asm volatile("cp.async.cg.shared.global [%0], [%1], 16;" :: "r"(s), "l"(g));
}
#define LDM4(r, addr)                                                         \
    asm volatile("ldmatrix.sync.aligned.m8n8.x4.shared.b16 {%0,%1,%2,%3}, [%4];" \
                 : "=r"((r)[0]), "=r"((r)[1]), "=r"((r)[2]), "=r"((r)[3])     \
                 : "r"(addr))
#define MMAF16(c, a, b)                                                       \
    asm volatile("mma.sync.aligned.m16n8k16.row.col.f32.f16.f16.f32 "         \
                 "{%0,%1,%2,%3},{%4,%5,%6,%7},{%8,%9},{%0,%1,%2,%3};"         \
                 : "+f"((c)[0]), "+f"((c)[1]), "+f"((c)[2]), "+f"((c)[3])     \
                 : "r"((a)[0]), "r"((a)[1]), "r"((a)[2]), "r"((a)[3]),        \
                   "r"((b)[0]), "r"((b)[1]))

// 64-byte rows, 16B chunks, chunk ^= (row>>1)&3 -> ldmatrix conflict-free
__device__ __forceinline__ uint32_t tile_off(int row, int chunk) {
    return (uint32_t)(row * 64 + ((chunk ^ ((row >> 1) & 3)) * 16));
}

// ---------------------------------------------------------------------------
// dtype detection + zeroing of g_deg / g_flag (block 0 detects, all zero)
// ---------------------------------------------------------------------------
__global__ void k_detect(const unsigned* __restrict__ ei,
                         const unsigned* __restrict__ bat, int E, int N) {
    int gid = blockIdx.x * blockDim.x + threadIdx.x;
    for (int i = gid; i < MAXN; i += gridDim.x * blockDim.x) g_deg[i] = 0;
    if (gid < 64) g_flag[gid] = 0;
    if (blockIdx.x == 0) {
        __shared__ int s_ei, s_b;
        if (threadIdx.x == 0) { s_ei = 0; s_b = 0; }
        __syncthreads();
        int ne = (E < 1024) ? E : 1024;
        for (int i = threadIdx.x; i < ne; i += blockDim.x)
            if (ei[2 * i + 1]) atomicOr(&s_ei, 1);
        int base = N / 2 - 256; if (base < 0) base = 0;
        int nb2 = (N / 2 > 256) ? 256 : N / 2;
        for (int j = threadIdx.x; j < nb2; j += blockDim.x)
            if (bat[2 * (base + j) + 1]) atomicOr(&s_b, 1);
        __syncthreads();
        if (threadIdx.x == 0) { g_ei64 = s_ei ? 0 : 1; g_b64 = s_b ? 0 : 1; }
    }
}

__device__ __forceinline__ int load_idx(const void* p, int i, int is64) {
    return is64 ? (int)((const long long*)p)[i] : ((const int*)p)[i];
}

// ---------------------------------------------------------------------------
// CSR-by-dst preprocessing: 2 edges/thread for MLP
// ---------------------------------------------------------------------------
__global__ void k_hist(const void* __restrict__ ei, int E) {
    int base = (blockIdx.x * blockDim.x + threadIdx.x) * 2;
    if (base >= E) return;
    int is64 = g_ei64;
    int d0 = load_idx(ei, E + base, is64);
    int d1 = (base + 1 < E) ? load_idx(ei, E + base + 1, is64) : -1;
    atomicAdd(&g_deg[d0], 1);
    if (d1 >= 0) atomicAdd(&g_deg[d1], 1);
}

// Single-pass exclusive scan: two-level warp-shuffle scan + warp-parallel
// decoupled lookback. All <=64 blocks resident in wave 1; each publishes
// (blocksum+1) into its flag word BEFORE polling, so no deadlock.
__global__ void k_scan1(const int* __restrict__ in, int* __restrict__ off,
                        int* __restrict__ cur, int n, int E) {
    __shared__ int wsum[32];
    __shared__ int woff_s[32];
    __shared__ int s_pfx;
    int bid = blockIdx.x;
    int tid = threadIdx.x;
    int lane = tid & 31, wid = tid >> 5;
    int gid = bid * 1024 + tid;
    int v = (gid < n) ? in[gid] : 0;
    int incl = v;
    #pragma unroll
    for (int d = 1; d < 32; d <<= 1) {
        int t = __shfl_up_sync(0xFFFFFFFFu, incl, d);
        if (lane >= d) incl += t;
    }
    if (lane == 31) wsum[wid] = incl;
    __syncthreads();
    if (wid == 0) {
        int w = wsum[lane];
        int winc = w;
        #pragma unroll
        for (int d = 1; d < 32; d <<= 1) {
            int t = __shfl_up_sync(0xFFFFFFFFu, winc, d);
            if (lane >= d) winc += t;
        }
        woff_s[lane] = winc - w;                      // exclusive warp offset
        int total = __shfl_sync(0xFFFFFFFFu, winc, 31);
        if (lane == 0) atomicExch(&g_flag[bid], total + 1);
        int pfx = 0;
        for (int i = lane; i < bid; i += 32) {
            int f;
            while ((f = atomicAdd(&g_flag[i], 0)) == 0) {}
            pfx += f - 1;
        }
        #pragma unroll
        for (int o = 16; o > 0; o >>= 1)
            pfx += __shfl_down_sync(0xFFFFFFFFu, pfx, o);
        if (lane == 0) s_pfx = pfx;
    }
    __syncthreads();
    if (gid < n) {
        int o = s_pfx + woff_s[wid] + incl - v;
        off[gid] = o;
        cur[gid] = o;
    }
    if (bid == (int)gridDim.x - 1 && tid == 1023) off[n] = E;
}

__global__ void k_scatter(const void* __restrict__ ei, int E) {
    int base = (blockIdx.x * blockDim.x + threadIdx.x) * 2;
    if (base >= E) return;
    int is64 = g_ei64;
    int s0 = load_idx(ei, base, is64);
    int d0 = load_idx(ei, E + base, is64);
    int has1 = (base + 1 < E);
    int s1 = has1 ? load_idx(ei, base + 1, is64) : 0;
    int d1 = has1 ? load_idx(ei, E + base + 1, is64) : 0;
    int deg0 = g_deg[s0];
    int deg1 = has1 ? g_deg[s1] : 0;
    int p0 = atomicAdd(&g_cur[d0], 1);
    int p1 = has1 ? atomicAdd(&g_cur[d1], 1) : 0;
    g_sw[p0] = make_int2(s0, __float_as_int(rsqrtf((float)(deg0 + 1))));
    if (has1)
        g_sw[p1] = make_int2(s1, __float_as_int(rsqrtf((float)(deg1 + 1))));
}

// All three weights, transposed to [N x K] fp16, in one launch.
__global__ void k_cvtW(const float* __restrict__ W1, const float* __restrict__ W2,
                       const float* __restrict__ W3) {
    int t = blockIdx.x * blockDim.x + threadIdx.x;
    if (t < 131072) {
        int n = t >> 9, k = t & 511;
        g_B1[t] = __float2half_rn(W1[(size_t)k * 256 + n]);
    } else if (t < 131072 + 32768) {
        int u = t - 131072;
        int n = u >> 8, k = u & 255;
        g_B2[u] = __float2half_rn(W2[(size_t)k * 128 + n]);
    } else if (t < 131072 + 32768 + 8192) {
        int u = t - 163840;
        int n = u >> 7, k = u & 127;
        g_B3[u] = __float2half_rn(W3[(size_t)k * 64 + n]);
    }
}

// ---------------------------------------------------------------------------
// HMMA GEMM: C[M,N] = A[M,K] @ B[N,K]^T, fp32 accum, fp16 out.
// Grid (n-tiles, m-tiles); bn fastest for L2 reuse of A.
// CVT=true: A fp32 in gmem, register-staged LDG->cvt->STS double-buffered.
// ---------------------------------------------------------------------------
template<int BN, bool CVT>
__global__ void __launch_bounds__(256, 1) k_gemm_mma(
    const void* __restrict__ Av, const __half* __restrict__ B,
    __half* __restrict__ C, int M, int N, int K)
{
    constexpr int SS = 8192 + BN * 64;
    constexpr int NT = BN / 16;
    constexpr int WN = BN / 2;
    extern __shared__ char smem[];
    uint32_t sb = smem_u32(smem);
    int tid = threadIdx.x, lane = tid & 31, wid = tid >> 5;
    int bm = blockIdx.y * 128, bn = blockIdx.x * BN;
    int warp_m = wid & 3, warp_n = wid >> 2;
    const __half* A = (const __half*)Av;
    const float* Af = (const float*)Av;

    float acc[2][NT][4] = {};
    const int KC = K >> 5;
    float4 a4[4];

    auto ldgA = [&](int it) {
        int k0 = it << 5;
        #pragma unroll
        for (int u = 0; u < 4; u++) {
            int c = u * 256 + tid;
            int row = c >> 3, ch8 = c & 7;
            int grow = bm + row;
            if (grow < M)
                a4[u] = *(const float4*)(Af + (size_t)grow * K + k0 + ch8 * 4);
            else
                a4[u] = make_float4(0.f, 0.f, 0.f, 0.f);
        }
    };
    auto stsA = [&](int s) {
        uint32_t base = sb + s * SS;
        #pragma unroll
        for (int u = 0; u < 4; u++) {
            int c = u * 256 + tid;
            int row = c >> 3, ch8 = c & 7;
            uint32_t off = tile_off(row, ch8 >> 1) + (ch8 & 1) * 8;
            __half2 h0 = __floats2half2_rn(a4[u].x, a4[u].y);
            __half2 h1 = __floats2half2_rn(a4[u].z, a4[u].w);
            asm volatile("st.shared.v2.b32 [%0], {%1,%2};"
                         :: "r"(base + off), "r"(*(uint32_t*)&h0), "r"(*(uint32_t*)&h1));
        }
    };
    auto ldA_async = [&](int it, int s) {
        int k0 = it << 5;
        uint32_t base = sb + s * SS;
        #pragma unroll
        for (int u = 0; u < 2; u++) {
            int c = tid * 2 + u;
            int row = c >> 2, ch = c & 3;
            cpa16(base + tile_off(row, ch), A + (size_t)(bm + row) * K + k0 + ch * 8);
        }
    };
    auto ldB = [&](int it, int s) {
        int k0 = it << 5;
        uint32_t base = sb + s * SS;
        #pragma unroll
        for (int u = 0; u < BN / 64; u++) {
            int c = tid + u * 256;
            int row = c >> 2, ch = c & 3;
            cpa16(base + 8192 + tile_off(row, ch), B + (size_t)(bn + row) * K + k0 + ch * 8);
        }
    };

    if constexpr (CVT) {
        ldgA(0);
        ldB(0, 0);
        asm volatile("cp.async.commit_group;");
        stsA(0);
    } else {
        ldA_async(0, 0);
        ldB(0, 0);
        asm volatile("cp.async.commit_group;");
    }

    int a_row = warp_m * 32 + (lane & 15);
    int a_chi = lane >> 4;
    int blk = lane >> 3;
    int b_rl = ((blk >> 1) * 8) + (lane & 7);
    int b_chi = blk & 1;

    for (int it = 0; it < KC; it++) {
        int s = it & 1;
        if (it + 1 < KC) {
            if constexpr (CVT) {
                ldgA(it + 1);
                ldB(it + 1, s ^ 1);
            } else {
                ldA_async(it + 1, s ^ 1);
                ldB(it + 1, s ^ 1);
            }
            asm volatile("cp.async.commit_group;");
            asm volatile("cp.async.wait_group 1;");
        } else {
            asm volatile("cp.async.wait_group 0;");
        }
        __syncthreads();
        uint32_t base = sb + s * SS;
        #pragma unroll
        for (int kk = 0; kk < 2; kk++) {
            uint32_t af[2][4];
            int ach = kk * 2 + a_chi;
            #pragma unroll
            for (int mt = 0; mt < 2; mt++) {
                uint32_t off = tile_off(a_row + mt * 16, ach);
                LDM4(af[mt], base + off);
            }
            #pragma unroll
            for (int h = 0; h < NT / 4; h++) {
                uint32_t bf[4][2];
                #pragma unroll
                for (int nt2 = 0; nt2 < 2; nt2++) {
                    uint32_t r4[4];
                    int brow = warp_n * WN + h * 32 + nt2 * 16 + b_rl;
                    uint32_t off = tile_off(brow, kk * 2 + b_chi);
                    LDM4(r4, base + 8192 + off);
                    bf[nt2 * 2][0] = r4[0]; bf[nt2 * 2][1] = r4[1];
                    bf[nt2 * 2 + 1][0] = r4[2]; bf[nt2 * 2 + 1][1] = r4[3];
                }
                #pragma unroll
                for (int mt = 0; mt < 2; mt++)
                    #pragma unroll
                    for (int j = 0; j < 4; j++)
                        MMAF16(acc[mt][h * 4 + j], af[mt], bf[j]);
            }
        }
        __syncthreads();
        if constexpr (CVT) {
            if (it + 1 < KC) stsA(s ^ 1);
        }
    }

    #pragma unroll
    for (int mt = 0; mt < 2; mt++)
        #pragma unroll
        for (int nt = 0; nt < NT; nt++) {
            int row0 = bm + warp_m * 32 + mt * 16 + (lane >> 2);
            int col = bn + warp_n * WN + nt * 8 + (lane & 3) * 2;
            if (row0 < M)
                *(__half2*)(C + (size_t)row0 * N + col) =
                    __floats2half2_rn(acc[mt][nt][0], acc[mt][nt][1]);
            if (row0 + 8 < M)
                *(__half2*)(C + (size_t)(row0 + 8) * N + col) =
                    __floats2half2_rn(acc[mt][nt][2], acc[mt][nt][3]);
        }
}

// ---------------------------------------------------------------------------
// Aggregation over fp16 H: Out[v] = dinv[v]*(dinv[v]*H[v] + sum wt*H[src]) + b
// Each thread covers 8 features (one uint4); fp32 accumulate; packed (src,wt)
// edge records; 8x unrolled gather for MLP.
// ---------------------------------------------------------------------------
__global__ void k_agg(const __half* __restrict__ Hin, float* __restrict__ OutF,
                      __half* __restrict__ OutH,
                      const float* __restrict__ bias, int N, int Mpad, int relu) {
    int v = blockIdx.x * blockDim.y + threadIdx.y;
    if (v >= Mpad) return;
    int F8 = blockDim.x;
    int x = threadIdx.x;
    int F = F8 * 8;
    if (v >= N) {
        if (OutH)
            ((uint4*)(OutH + (size_t)v * F))[x] = make_uint4(0, 0, 0, 0);
        return;
    }
    const uint4* H4 = (const uint4*)Hin;
    float dv = rsqrtf((float)(g_deg[v] + 1));
    float acc[8];
    {
        uint4 hv = H4[(size_t)v * F8 + x];
        const __half2* p = (const __half2*)&hv;
        #pragma unroll
        for (int q = 0; q < 4; q++) {
            float2 f = __half22float2(p[q]);
            acc[q * 2] = dv * f.x;
            acc[q * 2 + 1] = dv * f.y;
        }
    }
    int e = g_off[v], end = g_off[v + 1];
    for (; e + 7 < end; e += 8) {
        int2 sw[8]; uint4 hv[8];
        #pragma unroll
        for (int j = 0; j < 8; j++)
            sw[j] = __ldg(&g_sw[e + j]);
        #pragma unroll
        for (int j = 0; j < 8; j++)
            hv[j] = H4[(size_t)sw[j].x * F8 + x];
        #pragma unroll
        for (int j = 0; j < 8; j++) {
            float w = __int_as_float(sw[j].y);
            const __half2* p = (const __half2*)&hv[j];
            #pragma unroll
            for (int q = 0; q < 4; q++) {
                float2 f = __half22float2(p[q]);
                acc[q * 2]     += w * f.x;
                acc[q * 2 + 1] += w * f.y;
            }
        }
    }
    for (; e + 3 < end; e += 4) {
        int2 sw[4]; uint4 hv[4];
        #pragma unroll
        for (int j = 0; j < 4; j++)
            sw[j] = __ldg(&g_sw[e + j]);
        #pragma unroll
        for (int j = 0; j < 4; j++)
            hv[j] = H4[(size_t)sw[j].x * F8 + x];
        #pragma unroll
        for (int j = 0; j < 4; j++) {
            float w = __int_as_float(sw[j].y);
            const __half2* p = (const __half2*)&hv[j];
            #pragma unroll
            for (int q = 0; q < 4; q++) {
                float2 f = __half22float2(p[q]);
                acc[q * 2]     += w * f.x;
                acc[q * 2 + 1] += w * f.y;
            }
        }
    }
    for (; e < end; e++) {
        int2 sw = __ldg(&g_sw[e]);
        float w = __int_as_float(sw.y);
        uint4 h0 = H4[(size_t)sw.x * F8 + x];
        const __half2* p0 = (const __half2*)&h0;
        #pragma unroll
        for (int q = 0; q < 4; q++) {
            float2 f0 = __half22float2(p0[q]);
            acc[q * 2]     += w * f0.x;
            acc[q * 2 + 1] += w * f0.y;
        }
    }
    float o[8];
    {
        float4 b0 = ((const float4*)bias)[x * 2];
        float4 b1 = ((const float4*)bias)[x * 2 + 1];
        o[0] = dv * acc[0] + b0.x; o[1] = dv * acc[1] + b0.y;
        o[2] = dv * acc[2] + b0.z; o[3] = dv * acc[3] + b0.w;
        o[4] = dv * acc[4] + b1.x; o[5] = dv * acc[5] + b1.y;
        o[6] = dv * acc[6] + b1.z; o[7] = dv * acc[7] + b1.w;
    }
    if (relu) {
        #pragma unroll
        for (int q = 0; q < 8; q++) o[q] = fmaxf(o[q], 0.f);
    }
    if (OutF) {
        float4* d = (float4*)(OutF + (size_t)v * F + x * 8);
        d[0] = make_float4(o[0], o[1], o[2], o[3]);
        d[1] = make_float4(o[4], o[5], o[6], o[7]);
    }
    if (OutH) {
        __half2 hh[4];
        #pragma unroll
        for (int q = 0; q < 4; q++)
            hh[q] = __floats2half2_rn(o[q * 2], o[q * 2 + 1]);
        ((uint4*)(OutH + (size_t)v * F))[x] = *(uint4*)hh;
    }
}

// ---------------------------------------------------------------------------
// Fused mean-pool + head: one block per graph (batch sorted).
// ---------------------------------------------------------------------------
__global__ void k_poolfinal(const float* __restrict__ Afin,
                            const void* __restrict__ bat,
                            const float* __restrict__ Wl,
                            const float* __restrict__ bl,
                            float* __restrict__ out, int N) {
    int g = blockIdx.x;
    int t = threadIdx.x;
    int is64 = g_b64;
    int lo = 0, hi = N;
    while (lo < hi) { int m = (lo + hi) >> 1; if (load_idx(bat, m, is64) < g) lo = m + 1; else hi = m; }
    int lo2 = lo, hi2 = N;
    while (lo2 < hi2) { int m = (lo2 + hi2) >> 1; if (load_idx(bat, m, is64) < g + 1) lo2 = m + 1; else hi2 = m; }
    int f = t & 63, seg = t >> 6;
    float acc = 0.f;
    for (int v = lo + seg; v < lo2; v += 4)
        acc += Afin[(size_t)v * 64 + f];
    __shared__ float sm[256];
    __shared__ float pooled[64];
    sm[t] = acc;
    __syncthreads();
    if (t < 64)
        pooled[t] = sm[t] + sm[t + 64] + sm[t + 128] + sm[t + 192];
    __syncthreads();
    if (t < 2) {
        float cnt = fmaxf((float)(lo2 - lo), 1.0f);
        float s = 0.f;
        #pragma unroll
        for (int ff = 0; ff < 64; ff++) s += pooled[ff] * Wl[ff * 2 + t];
        out[g * 2 + t] = s / cnt + bl[t];
    }
}

// ---------------------------------------------------------------------------
// Orchestration: one side stream (CSR), everything else on stream 0.
// ---------------------------------------------------------------------------
extern "C" void kernel_launch(void* const* d_in, const int* in_sizes, int n_in,
                              void* d_out, int out_size) {
    const float* x   = (const float*)d_in[0];
    const void*  ei  = d_in[1];
    const void*  bat = d_in[2];
    const float* W1 = (const float*)d_in[3];
    const float* b1 = (const float*)d_in[4];
    const float* W2 = (const float*)d_in[5];
    const float* b2 = (const float*)d_in[6];
    const float* W3 = (const float*)d_in[7];
    const float* b3 = (const float*)d_in[8];
    const float* Wl = (const float*)d_in[9];
    const float* bl = (const float*)d_in[10];
    float* out = (float*)d_out;

    int N = in_sizes[0] / 512;
    int E = in_sizes[1] / 2;
    int G = out_size / 2;
    int mt = (N + 127) / 128;
    int Mpad = mt * 128;

    static int inited = 0;
    static cudaStream_t s2;
    static cudaEvent_t ev1, ev_csr;
    if (!inited) {
        cudaFuncSetAttribute((const void*)k_gemm_mma<128, true>,
                             cudaFuncAttributeMaxDynamicSharedMemorySize, 32768);
        cudaFuncSetAttribute((const void*)k_gemm_mma<128, false>,
                             cudaFuncAttributeMaxDynamicSharedMemorySize, 32768);
        cudaFuncSetAttribute((const void*)k_gemm_mma<64, false>,
                             cudaFuncAttributeMaxDynamicSharedMemorySize, 24576);
        cudaStreamCreateWithFlags(&s2, cudaStreamNonBlocking);
        cudaEventCreateWithFlags(&ev1, cudaEventDisableTiming);
        cudaEventCreateWithFlags(&ev_csr, cudaEventDisableTiming);
        inited = 1;
    }

    void *p_deg, *p_off, *p_cur, *p_H, *p_A, *p_X, *p_B1, *p_B2, *p_B3;
    cudaGetSymbolAddress(&p_deg, g_deg);
    cudaGetSymbolAddress(&p_off, g_off);
    cudaGetSymbolAddress(&p_cur, g_cur);
    cudaGetSymbolAddress(&p_H, g_H);
    cudaGetSymbolAddress(&p_A, g_A);
    cudaGetSymbolAddress(&p_X, g_X);
    cudaGetSymbolAddress(&p_B1, g_B1);
    cudaGetSymbolAddress(&p_B2, g_B2);
    cudaGetSymbolAddress(&p_B3, g_B3);

    // ---- fork: CSR build on side stream (gates agg1 only) ---------------
    cudaEventRecord(ev1, 0);
    cudaStreamWaitEvent(s2, ev1, 0);
    k_detect<<<64, 256, 0, s2>>>((const unsigned*)ei, (const unsigned*)bat, E, N);
    k_hist<<<(E / 2 + 255) / 256, 256, 0, s2>>>(ei, E);
    int nb = (N + 1023) / 1024;
    k_scan1<<<nb, 1024, 0, s2>>>((const int*)p_deg, (int*)p_off, (int*)p_cur, N, E);
    k_scatter<<<(E / 2 + 255) / 256, 256, 0, s2>>>(ei, E);
    cudaEventRecord(ev_csr, s2);

    // ---- stream 0: weight convert + layer-1 GEMM (fused fp32->fp16) -----
    k_cvtW<<<(172032 + 255) / 256, 256>>>(W1, W2, W3);
    k_gemm_mma<128, true><<<dim3(2, mt), 256, 32768>>>(
        x, (const __half*)p_B1, (__half*)p_H, N, 256, 512);

    // ---- join: aggregation needs CSR ------------------------------------
    cudaStreamWaitEvent(0, ev_csr, 0);
    {
        int gb = (Mpad + 7) / 8;
        k_agg<<<gb, dim3(32, 8)>>>((const __half*)p_H, nullptr,
                                   (__half*)p_X, b1, N, Mpad, 1);
    }
    // ---- layer 2 --------------------------------------------------------
    {
        k_gemm_mma<128, false><<<dim3(1, mt), 256, 32768>>>(
            p_X, (const __half*)p_B2, (__half*)p_H, N, 128, 256);
        int gb = (Mpad + 15) / 16;
        k_agg<<<gb, dim3(16, 16)>>>((const __half*)p_H, nullptr,
                                    (__half*)p_X, b2, N, Mpad, 1);
    }
    // ---- layer 3 --------------------------------------------------------
    {
        k_gemm_mma<64, false><<<dim3(1, mt), 256, 24576>>>(
            p_X, (const __half*)p_B3, (__half*)p_H, N, 64, 128);
        int gb = (N + 31) / 32;
        k_agg<<<gb, dim3(8, 32)>>>((const __half*)p_H, (float*)p_A,
                                   nullptr, b3, N, N, 0);
    }

    // ---- fused pool + head ----------------------------------------------
    k_poolfinal<<<G, 256>>>((const float*)p_A, bat, Wl, bl, out, N);
}